// round 14
// baseline (speedup 1.0000x reference)
#include <cuda_runtime.h>
#include <cuda_fp16.h>
#include <cstdint>
#include <math.h>

// ---------------- problem constants ----------------
#define BB 2
#define TT 4096
#define DD 1024
#define HH 16
#define DHH 64
#define FF 4096
#define KC 2048
#define LL 2
#define MR (BB * KC)   // 4096 active rows total

// ---------------- device scratch (static, allowed) ----------------
__device__ float  g_logits[BB * TT];
__device__ int    g_sel[BB * KC];
__device__ float  g_gate[BB * KC];
__device__ float  g_h[MR * DD];                       // fp32 residual stream
__device__ __half g_y[MR * DD];                       // LN output / attn out (fp16)
__device__ __half g_qkv[MR * 3 * DD];                 // fp16
__device__ __half g_ff[(size_t)MR * FF];              // fp16
// transposed fp16 weights ([N][K] row-major)
__device__ __half g_wqkvt[LL * 3 * DD * DD];
__device__ __half g_w1t[(size_t)LL * FF * DD];
__device__ __half g_w2t[(size_t)LL * DD * FF];
__device__ __half g_wot[LL * DD * DD];

// ---------------- router logits ----------------
__global__ void router_kernel(const float* __restrict__ x,
                              const float* __restrict__ w,
                              const float* __restrict__ b) {
    int token = blockIdx.x;
    const float* xr = x + (size_t)token * DD;
    float s = 0.f;
    for (int i = threadIdx.x; i < DD; i += blockDim.x) s += xr[i] * w[i];
    __shared__ float red[8];
    for (int o = 16; o > 0; o >>= 1) s += __shfl_down_sync(0xffffffffu, s, o);
    if ((threadIdx.x & 31) == 0) red[threadIdx.x >> 5] = s;
    __syncthreads();
    if (threadIdx.x < 32) {
        float v = (threadIdx.x < 8) ? red[threadIdx.x] : 0.f;
        for (int o = 4; o > 0; o >>= 1) v += __shfl_down_sync(0xffffffffu, v, o);
        if (threadIdx.x == 0) g_logits[token] = v + b[0];
    }
}

// ---------------- top-K via in-shared bitonic sort ----------------
__device__ __forceinline__ unsigned int ford(float f) {
    unsigned int u = __float_as_uint(f);
    return (u & 0x80000000u) ? ~u : (u | 0x80000000u);
}

__global__ void topk_kernel() {
    __shared__ unsigned long long s[TT];
    int b = blockIdx.x;
    const float* lg = g_logits + b * TT;
    for (int i = threadIdx.x; i < TT; i += blockDim.x) {
        unsigned long long key = ((unsigned long long)ford(lg[i]) << 32) | (unsigned int)i;
        s[i] = key;
    }
    __syncthreads();
    for (int k = 2; k <= TT; k <<= 1) {
        for (int j = k >> 1; j > 0; j >>= 1) {
            for (int i = threadIdx.x; i < TT; i += blockDim.x) {
                int ixj = i ^ j;
                if (ixj > i) {
                    bool up = ((i & k) == 0);
                    unsigned long long a = s[i], c = s[ixj];
                    if ((a > c) == up) { s[i] = c; s[ixj] = a; }
                }
            }
            __syncthreads();
        }
    }
    for (int r = threadIdx.x; r < KC; r += blockDim.x) {
        unsigned long long key = s[TT - 1 - r];
        int idx = (int)(key & 0xffffffffu);
        g_sel[b * KC + r] = idx;
        float v = lg[idx];
        g_gate[b * KC + r] = 1.f / (1.f + expf(-v));
    }
}

// ---------------- gather active tokens ----------------
__global__ void gather_kernel(const float* __restrict__ x) {
    int row = blockIdx.x;
    int b = row / KC;
    int idx = g_sel[row];
    const float4* src = (const float4*)(x + ((size_t)b * TT + idx) * DD);
    float4* dst = (float4*)(g_h + (size_t)row * DD);
    for (int i = threadIdx.x; i < DD / 4; i += blockDim.x) dst[i] = src[i];
}

// ---------------- layernorm (fp32 in, fp16 out) ----------------
__global__ void ln_kernel(const float* __restrict__ inp,
                          const float* __restrict__ w,
                          const float* __restrict__ bia,
                          __half* __restrict__ out) {
    int row = blockIdx.x;
    const float* xr = inp + (size_t)row * DD;
    float vals[4];
    float s = 0.f, s2 = 0.f;
#pragma unroll
    for (int i = 0; i < 4; i++) {
        float v = xr[threadIdx.x + i * 256];
        vals[i] = v; s += v; s2 += v * v;
    }
    __shared__ float rs[8], rs2[8];
    for (int o = 16; o > 0; o >>= 1) {
        s  += __shfl_down_sync(0xffffffffu, s, o);
        s2 += __shfl_down_sync(0xffffffffu, s2, o);
    }
    if ((threadIdx.x & 31) == 0) { rs[threadIdx.x >> 5] = s; rs2[threadIdx.x >> 5] = s2; }
    __syncthreads();
    __shared__ float mu_s, rstd_s;
    if (threadIdx.x == 0) {
        float a = 0.f, c = 0.f;
        for (int i = 0; i < 8; i++) { a += rs[i]; c += rs2[i]; }
        float mu = a / DD;
        float var = c / DD - mu * mu;
        mu_s = mu; rstd_s = rsqrtf(var + 1e-5f);
    }
    __syncthreads();
    float mu = mu_s, rstd = rstd_s;
#pragma unroll
    for (int i = 0; i < 4; i++) {
        int c = threadIdx.x + i * 256;
        out[(size_t)row * DD + c] = __float2half((vals[i] - mu) * rstd * w[c] + bia[c]);
    }
}

// ---------------- weight transpose fp32 -> fp16 : dst[C][R] = src[R][C] ----------------
__global__ void transpose_w(const float* __restrict__ src, __half* __restrict__ dst,
                            int R, int C, long long sS, long long sD) {
    __shared__ float t[32][33];
    int z = blockIdx.z;
    src += (long long)z * sS;
    dst += (long long)z * sD;
    int rb = blockIdx.y * 32, cb = blockIdx.x * 32;
    int tx = threadIdx.x, ty = threadIdx.y;   // (32, 8)
#pragma unroll
    for (int i = 0; i < 4; i++)
        t[ty + i * 8][tx] = src[(long long)(rb + ty + i * 8) * C + cb + tx];
    __syncthreads();
#pragma unroll
    for (int i = 0; i < 4; i++)
        dst[(long long)(cb + ty + i * 8) * R + rb + tx] = __float2half(t[tx][ty + i * 8]);
}

// ---------------- mma / ldmatrix helpers ----------------
__device__ __forceinline__ void ldsm4(unsigned* r, unsigned addr) {
    asm volatile("ldmatrix.sync.aligned.m8n8.x4.shared.b16 {%0,%1,%2,%3}, [%4];"
                 : "=r"(r[0]), "=r"(r[1]), "=r"(r[2]), "=r"(r[3]) : "r"(addr));
}
__device__ __forceinline__ void ldsm4t(unsigned* r, unsigned addr) {
    asm volatile("ldmatrix.sync.aligned.m8n8.x4.trans.shared.b16 {%0,%1,%2,%3}, [%4];"
                 : "=r"(r[0]), "=r"(r[1]), "=r"(r[2]), "=r"(r[3]) : "r"(addr));
}
__device__ __forceinline__ void mma_f16(float* c, const unsigned* a, const unsigned* b) {
    asm volatile(
        "mma.sync.aligned.m16n8k16.row.col.f32.f16.f16.f32 "
        "{%0,%1,%2,%3}, {%4,%5,%6,%7}, {%8,%9}, {%0,%1,%2,%3};"
        : "+f"(c[0]), "+f"(c[1]), "+f"(c[2]), "+f"(c[3])
        : "r"(a[0]), "r"(a[1]), "r"(a[2]), "r"(a[3]), "r"(b[0]), "r"(b[1]));
}
__device__ __forceinline__ void cp16(uint32_t dst, const void* src) {
    asm volatile("cp.async.cg.shared.global [%0], [%1], 16;\n" :: "r"(dst), "l"(src));
}
__device__ __forceinline__ float gelu_f(float x) {
    const float c = 0.7978845608028654f;
    float t = tanhf(c * (x + 0.044715f * x * x * x));
    return 0.5f * x * (1.f + t);
}
__device__ __forceinline__ unsigned pack_h2(float a, float b) {
    __half2 h = __halves2half2(__float2half(a), __float2half(b));
    return *(unsigned*)&h;
}

// ============================================================================
// FP16 tensor-core GEMM (NT): C = alpha*(A @ B^T) [+Cin] [gelu]
// A [M,Kd] fp16 row-major lda, B [N,Kd] fp16 row-major ldb.
// CTA tile 128 x TILEN, K-tile 32, 256 threads, 3-stage cp.async pipeline.
// TILEN=256: 2x4 warps, warp 64x64.  TILEN=128: 2x4 warps, warp 64x32.
// M mult 128, N mult TILEN, Kd mult 32.
// ============================================================================
template<int TILEN>
__global__ void __launch_bounds__(256) h_gemm(
    const __half* __restrict__ A, const __half* __restrict__ B,
    const float* __restrict__ Cin, void* __restrict__ CoutV,
    int Kd, int lda, int ldb, int ldc,
    float alpha, int addC, int doGelu, int outHalf)
{
    constexpr int PB2 = 40;                // smem pitch in halves (80 B)
    constexpr int NP  = TILEN / 64;        // B ldsm.x4 frags per warp (2 or 4)
    constexpr int ASZ = 128 * PB2;         // halves per A stage
    constexpr int BSZ = TILEN * PB2;       // halves per B stage
    constexpr int STG = ASZ + BSZ;

    extern __shared__ __half dsm[];
    unsigned sb = (unsigned)__cvta_generic_to_shared(dsm);

    const float* CinP = Cin;
    float*  CF = (float*)CoutV;
    __half* CH = (__half*)CoutV;

    int bm = blockIdx.y * 128;
    int bn = blockIdx.x * TILEN;

    int tid = threadIdx.x;
    int lane = tid & 31;
    int warp = tid >> 5;
    int warpM = (warp >> 2) * 64;
    int warpN = (warp & 3) * (TILEN / 4);

    // ldsm per-lane offsets (stage-relative bytes)
    unsigned aOff[4];
#pragma unroll
    for (int mt = 0; mt < 4; mt++)
        aOff[mt] = (unsigned)(((warpM + mt * 16 + (lane & 15)) * PB2 + (lane >> 4) * 8) * 2);
    unsigned bOff[NP];
#pragma unroll
    for (int np = 0; np < NP; np++)
        bOff[np] = (unsigned)(ASZ * 2 +
                   ((warpN + np * 16 + (lane & 7) + ((lane >> 4) & 1) * 8) * PB2
                    + ((lane >> 3) & 1) * 8) * 2);

    float acc[4][2 * NP][4];
#pragma unroll
    for (int i = 0; i < 4; i++)
#pragma unroll
        for (int j = 0; j < 2 * NP; j++)
#pragma unroll
            for (int q = 0; q < 4; q++) acc[i][j][q] = 0.f;

    int srow = tid >> 1;          // 0..127
    int scp  = (tid & 1) * 2;     // chunk base (2 chunks of 16B per pass)

    auto load_tile = [&](int kt, int st) {
        int k0 = kt * 32;
        unsigned ab = sb + (unsigned)(st * STG * 2);
        unsigned bb2 = ab + (unsigned)(ASZ * 2);
#pragma unroll
        for (int c = 0; c < 2; c++)
            cp16(ab + (unsigned)((srow * PB2 + (scp + c) * 8) * 2),
                 A + (long long)(bm + srow) * lda + k0 + (scp + c) * 8);
#pragma unroll
        for (int p = 0; p < TILEN / 128; p++) {
            int br = srow + p * 128;
#pragma unroll
            for (int c = 0; c < 2; c++)
                cp16(bb2 + (unsigned)((br * PB2 + (scp + c) * 8) * 2),
                     B + (long long)(bn + br) * ldb + k0 + (scp + c) * 8);
        }
        asm volatile("cp.async.commit_group;");
    };

    int KT = Kd >> 5;
    load_tile(0, 0);
    if (KT > 1) load_tile(1, 1);

    for (int kt = 0; kt < KT; kt++) {
        if (kt + 1 < KT) asm volatile("cp.async.wait_group 1;");
        else             asm volatile("cp.async.wait_group 0;");
        __syncthreads();
        if (kt + 2 < KT) load_tile(kt + 2, (kt + 2) % 3);

        unsigned base = sb + (unsigned)((kt % 3) * STG * 2);
#pragma unroll
        for (int k16 = 0; k16 < 2; k16++) {
            unsigned aF[4][4];
#pragma unroll
            for (int mt = 0; mt < 4; mt++)
                ldsm4(aF[mt], base + aOff[mt] + k16 * 32);
            unsigned bF[NP][4];
#pragma unroll
            for (int np = 0; np < NP; np++)
                ldsm4(bF[np], base + bOff[np] + k16 * 32);
#pragma unroll
            for (int mt = 0; mt < 4; mt++)
#pragma unroll
                for (int np = 0; np < NP; np++) {
                    mma_f16(acc[mt][np * 2 + 0], aF[mt], &bF[np][0]);
                    mma_f16(acc[mt][np * 2 + 1], aF[mt], &bF[np][2]);
                }
        }
    }

    int grp = lane >> 2, c2 = (lane & 3) * 2;
#pragma unroll
    for (int mt = 0; mt < 4; mt++) {
#pragma unroll
        for (int j = 0; j < 2 * NP; j++) {
            int col = bn + warpN + (j >> 1) * 16 + (j & 1) * 8 + c2;
            long long r0 = (long long)(bm + warpM + mt * 16 + grp) * ldc + col;
            long long r1 = r0 + 8LL * ldc;
            float v00 = acc[mt][j][0] * alpha, v01 = acc[mt][j][1] * alpha;
            float v10 = acc[mt][j][2] * alpha, v11 = acc[mt][j][3] * alpha;
            if (doGelu) {
                v00 = gelu_f(v00); v01 = gelu_f(v01);
                v10 = gelu_f(v10); v11 = gelu_f(v11);
            }
            if (addC) {
                float2 ci0 = *(const float2*)(CinP + r0);
                float2 ci1 = *(const float2*)(CinP + r1);
                v00 += ci0.x; v01 += ci0.y;
                v10 += ci1.x; v11 += ci1.y;
            }
            if (outHalf) {
                *(__half2*)(CH + r0) = __halves2half2(__float2half(v00), __float2half(v01));
                *(__half2*)(CH + r1) = __halves2half2(__float2half(v10), __float2half(v11));
            } else {
                *(float2*)(CF + r0) = make_float2(v00, v01);
                *(float2*)(CF + r1) = make_float2(v10, v11);
            }
        }
    }
}

// ============================================================================
// Fused FlashAttention-2 over the active token set (unchanged from R12).
// ============================================================================
#define FPITCH 72   // smem pitch in halves

__global__ void __launch_bounds__(256) flash_kernel(
    const __half* __restrict__ qkv, __half* __restrict__ yout)
{
    extern __shared__ __half fsm[];
    __half* Qs = fsm;
    __half* Ks0 = fsm + 128 * FPITCH;
    __half* Ks1 = fsm + 2 * 128 * FPITCH;
    __half* Vs0 = fsm + 3 * 128 * FPITCH;
    __half* Vs1 = fsm + 4 * 128 * FPITCH;

    int bh = blockIdx.y;
    int b = bh / HH, h = bh % HH;
    const __half* Qg = qkv + (size_t)b * KC * 3 * DD + h * DHH;
    const __half* Kg = Qg + DD;
    const __half* Vg = Qg + 2 * DD;
    int q0 = blockIdx.x * 128;

    int tid = threadIdx.x;
    int lane = tid & 31, warp = tid >> 5;
    int wq = warp * 16;

    unsigned qB = (unsigned)__cvta_generic_to_shared(Qs);
    unsigned kB0 = (unsigned)__cvta_generic_to_shared(Ks0);
    unsigned kB1 = (unsigned)__cvta_generic_to_shared(Ks1);
    unsigned vB0 = (unsigned)__cvta_generic_to_shared(Vs0);
    unsigned vB1 = (unsigned)__cvta_generic_to_shared(Vs1);

    int sr = tid >> 2;           // row 0..63 (+64 second pass)
    int sq = tid & 3;            // chunk-pair index

    auto load_q = [&]() {
#pragma unroll
        for (int p = 0; p < 2; p++)
#pragma unroll
            for (int c = 0; c < 2; c++)
                cp16(qB + (unsigned)(((sr + p * 64) * FPITCH + (sq * 2 + c) * 8) * 2),
                     Qg + (long long)(q0 + sr + p * 64) * (3 * DD) + (sq * 2 + c) * 8);
    };
    auto load_kv = [&](int it, unsigned kb, unsigned vb) {
#pragma unroll
        for (int p = 0; p < 2; p++) {
            int r0 = it * 128 + sr + p * 64;
#pragma unroll
            for (int c = 0; c < 2; c++)
                cp16(kb + (unsigned)(((sr + p * 64) * FPITCH + (sq * 2 + c) * 8) * 2),
                     Kg + (long long)r0 * (3 * DD) + (sq * 2 + c) * 8);
#pragma unroll
            for (int c = 0; c < 2; c++)
                cp16(vb + (unsigned)(((sr + p * 64) * FPITCH + (sq * 2 + c) * 8) * 2),
                     Vg + (long long)r0 * (3 * DD) + (sq * 2 + c) * 8);
        }
    };

    unsigned qAddr = qB + (unsigned)(((wq + (lane & 15)) * FPITCH + (lane >> 4) * 8) * 2);
    unsigned kLane = (unsigned)((((lane & 7) + ((lane >> 4) & 1) * 8) * FPITCH
                                 + ((lane >> 3) & 1) * 8) * 2);
    unsigned vLane = (unsigned)((((lane & 7) + ((lane >> 3) & 1) * 8) * FPITCH
                                 + (lane >> 4) * 8) * 2);

    float m0 = -1e30f, m1 = -1e30f, l0 = 0.f, l1 = 0.f;
    float O[8][4];
#pragma unroll
    for (int i = 0; i < 8; i++)
#pragma unroll
        for (int j = 0; j < 4; j++) O[i][j] = 0.f;

    const float LOG2E = 1.4426950408889634f;

    load_q();
    load_kv(0, kB0, vB0);
    asm volatile("cp.async.commit_group;");

    const int NIT = KC / 128;
    for (int it = 0; it < NIT; it++) {
        asm volatile("cp.async.wait_group 0;");
        __syncthreads();
        unsigned kb = (it & 1) ? kB1 : kB0;
        unsigned vb = (it & 1) ? vB1 : vB0;
        if (it + 1 < NIT) {
            load_kv(it + 1, (it & 1) ? kB0 : kB1, (it & 1) ? vB0 : vB1);
            asm volatile("cp.async.commit_group;");
        }

        float S[16][4];
#pragma unroll
        for (int i = 0; i < 16; i++)
#pragma unroll
            for (int j = 0; j < 4; j++) S[i][j] = 0.f;

#pragma unroll
        for (int dhc = 0; dhc < 4; dhc++) {
            unsigned qa[4];
            ldsm4(qa, qAddr + dhc * 32);
#pragma unroll
            for (int nt = 0; nt < 8; nt++) {
                unsigned kf[4];
                ldsm4(kf, kb + kLane + (unsigned)(nt * 16 * FPITCH * 2 + dhc * 32));
                mma_f16(S[2 * nt], qa, &kf[0]);
                mma_f16(S[2 * nt + 1], qa, &kf[2]);
            }
        }

        float mx0 = -1e30f, mx1 = -1e30f;
#pragma unroll
        for (int i = 0; i < 16; i++) {
#pragma unroll
            for (int j = 0; j < 4; j++) S[i][j] *= 0.125f;
            mx0 = fmaxf(mx0, fmaxf(S[i][0], S[i][1]));
            mx1 = fmaxf(mx1, fmaxf(S[i][2], S[i][3]));
        }
        mx0 = fmaxf(mx0, __shfl_xor_sync(0xffffffffu, mx0, 1));
        mx0 = fmaxf(mx0, __shfl_xor_sync(0xffffffffu, mx0, 2));
        mx1 = fmaxf(mx1, __shfl_xor_sync(0xffffffffu, mx1, 1));
        mx1 = fmaxf(mx1, __shfl_xor_sync(0xffffffffu, mx1, 2));
        float mn0 = fmaxf(m0, mx0), mn1 = fmaxf(m1, mx1);
        float sc0 = exp2f((m0 - mn0) * LOG2E);
        float sc1 = exp2f((m1 - mn1) * LOG2E);
        float sum0 = 0.f, sum1 = 0.f;
#pragma unroll
        for (int i = 0; i < 16; i++) {
            S[i][0] = exp2f((S[i][0] - mn0) * LOG2E);
            S[i][1] = exp2f((S[i][1] - mn0) * LOG2E);
            S[i][2] = exp2f((S[i][2] - mn1) * LOG2E);
            S[i][3] = exp2f((S[i][3] - mn1) * LOG2E);
            sum0 += S[i][0] + S[i][1];
            sum1 += S[i][2] + S[i][3];
        }
        sum0 += __shfl_xor_sync(0xffffffffu, sum0, 1);
        sum0 += __shfl_xor_sync(0xffffffffu, sum0, 2);
        sum1 += __shfl_xor_sync(0xffffffffu, sum1, 1);
        sum1 += __shfl_xor_sync(0xffffffffu, sum1, 2);
        l0 = l0 * sc0 + sum0;
        l1 = l1 * sc1 + sum1;
        m0 = mn0; m1 = mn1;
#pragma unroll
        for (int dn = 0; dn < 8; dn++) {
            O[dn][0] *= sc0; O[dn][1] *= sc0;
            O[dn][2] *= sc1; O[dn][3] *= sc1;
        }

#pragma unroll
        for (int kc = 0; kc < 8; kc++) {
            unsigned pa[4];
            pa[0] = pack_h2(S[2 * kc][0], S[2 * kc][1]);
            pa[1] = pack_h2(S[2 * kc][2], S[2 * kc][3]);
            pa[2] = pack_h2(S[2 * kc + 1][0], S[2 * kc + 1][1]);
            pa[3] = pack_h2(S[2 * kc + 1][2], S[2 * kc + 1][3]);
#pragma unroll
            for (int dn = 0; dn < 4; dn++) {
                unsigned vf[4];
                ldsm4t(vf, vb + vLane + (unsigned)(kc * 16 * FPITCH * 2 + dn * 32));
                mma_f16(O[2 * dn], pa, &vf[0]);
                mma_f16(O[2 * dn + 1], pa, &vf[2]);
            }
        }
        __syncthreads();
    }

    float inv0 = 1.f / l0, inv1 = 1.f / l1;
    int row0 = b * KC + q0 + wq + (lane >> 2);
    int row1 = row0 + 8;
    int colb = h * DHH + (lane & 3) * 2;
#pragma unroll
    for (int dn = 0; dn < 8; dn++) {
        int col = colb + dn * 8;
        *(__half2*)(yout + (size_t)row0 * DD + col) =
            __halves2half2(__float2half(O[dn][0] * inv0), __float2half(O[dn][1] * inv0));
        *(__half2*)(yout + (size_t)row1 * DD + col) =
            __halves2half2(__float2half(O[dn][2] * inv1), __float2half(O[dn][3] * inv1));
    }
}

// ---------------- gated scatter-add ----------------
__global__ void scatter_kernel(float* __restrict__ out) {
    int row = blockIdx.x;
    int b = row / KC;
    int idx = g_sel[row];
    float g = g_gate[row];
    float4* dst = (float4*)(out + ((size_t)b * TT + idx) * DD);
    const float4* src = (const float4*)(g_h + (size_t)row * DD);
    for (int i = threadIdx.x; i < DD / 4; i += blockDim.x) {
        float4 d = dst[i], s = src[i];
        d.x += g * s.x; d.y += g * s.y; d.z += g * s.z; d.w += g * s.w;
        dst[i] = d;
    }
}

// ---------------- host launcher ----------------
extern "C" void kernel_launch(void* const* d_in, const int* in_sizes, int n_in,
                              void* d_out, int out_size) {
    const float* x        = (const float*)d_in[0];
    const float* router_w = (const float*)d_in[1];
    const float* router_b = (const float*)d_in[2];
    const float* ln1_w    = (const float*)d_in[3];
    const float* ln1_b    = (const float*)d_in[4];
    const float* wqkv     = (const float*)d_in[5];
    const float* wo       = (const float*)d_in[6];
    const float* ln2_w    = (const float*)d_in[7];
    const float* ln2_b    = (const float*)d_in[8];
    const float* w1       = (const float*)d_in[9];
    const float* w2       = (const float*)d_in[10];
    float* out = (float*)d_out;

    float *p_h;
    __half *p_y, *p_qkv, *p_ff;
    __half *p_wqkvt, *p_w1t, *p_w2t, *p_wot;
    cudaGetSymbolAddress((void**)&p_h, g_h);
    cudaGetSymbolAddress((void**)&p_y, g_y);
    cudaGetSymbolAddress((void**)&p_qkv, g_qkv);
    cudaGetSymbolAddress((void**)&p_ff, g_ff);
    cudaGetSymbolAddress((void**)&p_wqkvt, g_wqkvt);
    cudaGetSymbolAddress((void**)&p_w1t, g_w1t);
    cudaGetSymbolAddress((void**)&p_w2t, g_w2t);
    cudaGetSymbolAddress((void**)&p_wot, g_wot);

    const int FSMEM = 5 * 128 * FPITCH * 2;            // 92160 B
    const int GSMEM256 = 3 * (128 + 256) * 40 * 2;     // 92160 B
    const int GSMEM128 = 3 * (128 + 128) * 40 * 2;     // 61440 B
    cudaFuncSetAttribute(flash_kernel, cudaFuncAttributeMaxDynamicSharedMemorySize, FSMEM);
    cudaFuncSetAttribute(h_gemm<256>, cudaFuncAttributeMaxDynamicSharedMemorySize, GSMEM256);
    cudaFuncSetAttribute(h_gemm<128>, cudaFuncAttributeMaxDynamicSharedMemorySize, GSMEM128);

    router_kernel<<<BB * TT, 256>>>(x, router_w, router_b);
    topk_kernel<<<BB, 1024>>>();
    gather_kernel<<<MR, 256>>>(x);

    // pre-transpose + fp16-convert weights: W[K,N] -> Wt[N,K]
    dim3 tb(32, 8);
    transpose_w<<<dim3(3 * DD / 32, DD / 32, LL), tb>>>(
        wqkv, p_wqkvt, DD, 3 * DD, (long long)DD * 3 * DD, (long long)3 * DD * DD);
    transpose_w<<<dim3(FF / 32, DD / 32, LL), tb>>>(
        w1, p_w1t, DD, FF, (long long)DD * FF, (long long)FF * DD);
    transpose_w<<<dim3(DD / 32, FF / 32, LL), tb>>>(
        w2, p_w2t, FF, DD, (long long)FF * DD, (long long)DD * FF);
    transpose_w<<<dim3(DD / 32, DD / 32, LL), tb>>>(
        wo, p_wot, DD, DD, (long long)DD * DD, (long long)DD * DD);

    for (int l = 0; l < LL; l++) {
        // --- attention sub-block ---
        ln_kernel<<<MR, 256>>>(p_h, ln1_w + l * DD, ln1_b + l * DD, p_y);

        // qkv = y @ Wqkv^T  (fp16 out)
        h_gemm<256><<<dim3(3 * DD / 256, MR / 128, 1), 256, GSMEM256>>>(
            p_y, p_wqkvt + (size_t)l * 3 * DD * DD, p_h, p_qkv,
            DD, DD, DD, 3 * DD, 1.f, 0, 0, 1);

        // fused attention -> y (fp16)
        flash_kernel<<<dim3(KC / 128, BB * HH), 256, FSMEM>>>(p_qkv, p_y);

        // h += O @ Wo^T (fp32 out + residual)
        h_gemm<128><<<dim3(DD / 128, MR / 128, 1), 256, GSMEM128>>>(
            p_y, p_wot + (size_t)l * DD * DD, p_h, p_h,
            DD, DD, DD, DD, 1.f, 1, 0, 0);

        // --- MLP sub-block ---
        ln_kernel<<<MR, 256>>>(p_h, ln2_w + l * DD, ln2_b + l * DD, p_y);

        // ff = gelu(y @ W1^T)  (fp16 out, gelu fused)
        h_gemm<256><<<dim3(FF / 256, MR / 128, 1), 256, GSMEM256>>>(
            p_y, p_w1t + (size_t)l * FF * DD, p_h, p_ff,
            DD, DD, DD, FF, 1.f, 0, 1, 1);

        // h += ff @ W2^T (fp32 out + residual)
        h_gemm<128><<<dim3(DD / 128, MR / 128, 1), 256, GSMEM128>>>(
            p_ff, p_w2t + (size_t)l * DD * FF, p_h, p_h,
            FF, FF, FF, DD, 1.f, 1, 0, 0);
    }

    cudaMemcpyAsync(out, x, (size_t)BB * TT * DD * sizeof(float),
                    cudaMemcpyDeviceToDevice, 0);
    scatter_kernel<<<MR, 256>>>(out);
}

// round 15
// speedup vs baseline: 1.0391x; 1.0391x over previous
#include <cuda_runtime.h>
#include <cuda_fp16.h>
#include <cstdint>
#include <math.h>

// ---------------- problem constants ----------------
#define BB 2
#define TT 4096
#define DD 1024
#define HH 16
#define DHH 64
#define FF 4096
#define KC 2048
#define LL 2
#define MR (BB * KC)   // 4096 active rows total

// ---------------- device scratch (static, allowed) ----------------
__device__ float  g_logits[BB * TT];
__device__ int    g_sel[BB * KC];
__device__ float  g_gate[BB * KC];
__device__ float  g_h[MR * DD];                       // fp32 residual stream
__device__ __half g_y[MR * DD];                       // LN output / attn out (fp16)
__device__ __half g_qkv[MR * 3 * DD];                 // fp16
__device__ __half g_ff[(size_t)MR * FF];              // fp16
// transposed fp16 weights ([N][K] row-major)
__device__ __half g_wqkvt[LL * 3 * DD * DD];
__device__ __half g_w1t[(size_t)LL * FF * DD];
__device__ __half g_w2t[(size_t)LL * DD * FF];
__device__ __half g_wot[LL * DD * DD];

// ---------------- router logits ----------------
__global__ void router_kernel(const float* __restrict__ x,
                              const float* __restrict__ w,
                              const float* __restrict__ b) {
    int token = blockIdx.x;
    const float* xr = x + (size_t)token * DD;
    float s = 0.f;
    for (int i = threadIdx.x; i < DD; i += blockDim.x) s += xr[i] * w[i];
    __shared__ float red[8];
    for (int o = 16; o > 0; o >>= 1) s += __shfl_down_sync(0xffffffffu, s, o);
    if ((threadIdx.x & 31) == 0) red[threadIdx.x >> 5] = s;
    __syncthreads();
    if (threadIdx.x < 32) {
        float v = (threadIdx.x < 8) ? red[threadIdx.x] : 0.f;
        for (int o = 4; o > 0; o >>= 1) v += __shfl_down_sync(0xffffffffu, v, o);
        if (threadIdx.x == 0) g_logits[token] = v + b[0];
    }
}

// ---------------- top-K via in-shared bitonic sort ----------------
__device__ __forceinline__ unsigned int ford(float f) {
    unsigned int u = __float_as_uint(f);
    return (u & 0x80000000u) ? ~u : (u | 0x80000000u);
}

__global__ void topk_kernel() {
    __shared__ unsigned long long s[TT];
    int b = blockIdx.x;
    const float* lg = g_logits + b * TT;
    for (int i = threadIdx.x; i < TT; i += blockDim.x) {
        unsigned long long key = ((unsigned long long)ford(lg[i]) << 32) | (unsigned int)i;
        s[i] = key;
    }
    __syncthreads();
    for (int k = 2; k <= TT; k <<= 1) {
        for (int j = k >> 1; j > 0; j >>= 1) {
            for (int i = threadIdx.x; i < TT; i += blockDim.x) {
                int ixj = i ^ j;
                if (ixj > i) {
                    bool up = ((i & k) == 0);
                    unsigned long long a = s[i], c = s[ixj];
                    if ((a > c) == up) { s[i] = c; s[ixj] = a; }
                }
            }
            __syncthreads();
        }
    }
    for (int r = threadIdx.x; r < KC; r += blockDim.x) {
        unsigned long long key = s[TT - 1 - r];
        int idx = (int)(key & 0xffffffffu);
        g_sel[b * KC + r] = idx;
        float v = lg[idx];
        g_gate[b * KC + r] = 1.f / (1.f + expf(-v));
    }
}

// ---------------- gather active tokens ----------------
__global__ void gather_kernel(const float* __restrict__ x) {
    int row = blockIdx.x;
    int b = row / KC;
    int idx = g_sel[row];
    const float4* src = (const float4*)(x + ((size_t)b * TT + idx) * DD);
    float4* dst = (float4*)(g_h + (size_t)row * DD);
    for (int i = threadIdx.x; i < DD / 4; i += blockDim.x) dst[i] = src[i];
}

// ---------------- layernorm (fp32 in, fp16 out) ----------------
__global__ void ln_kernel(const float* __restrict__ inp,
                          const float* __restrict__ w,
                          const float* __restrict__ bia,
                          __half* __restrict__ out) {
    int row = blockIdx.x;
    const float* xr = inp + (size_t)row * DD;
    float vals[4];
    float s = 0.f, s2 = 0.f;
#pragma unroll
    for (int i = 0; i < 4; i++) {
        float v = xr[threadIdx.x + i * 256];
        vals[i] = v; s += v; s2 += v * v;
    }
    __shared__ float rs[8], rs2[8];
    for (int o = 16; o > 0; o >>= 1) {
        s  += __shfl_down_sync(0xffffffffu, s, o);
        s2 += __shfl_down_sync(0xffffffffu, s2, o);
    }
    if ((threadIdx.x & 31) == 0) { rs[threadIdx.x >> 5] = s; rs2[threadIdx.x >> 5] = s2; }
    __syncthreads();
    __shared__ float mu_s, rstd_s;
    if (threadIdx.x == 0) {
        float a = 0.f, c = 0.f;
        for (int i = 0; i < 8; i++) { a += rs[i]; c += rs2[i]; }
        float mu = a / DD;
        float var = c / DD - mu * mu;
        mu_s = mu; rstd_s = rsqrtf(var + 1e-5f);
    }
    __syncthreads();
    float mu = mu_s, rstd = rstd_s;
#pragma unroll
    for (int i = 0; i < 4; i++) {
        int c = threadIdx.x + i * 256;
        out[(size_t)row * DD + c] = __float2half((vals[i] - mu) * rstd * w[c] + bia[c]);
    }
}

// ---------------- weight transpose fp32 -> fp16 : dst[C][R] = src[R][C] ----------------
__global__ void transpose_w(const float* __restrict__ src, __half* __restrict__ dst,
                            int R, int C, long long sS, long long sD) {
    __shared__ float t[32][33];
    int z = blockIdx.z;
    src += (long long)z * sS;
    dst += (long long)z * sD;
    int rb = blockIdx.y * 32, cb = blockIdx.x * 32;
    int tx = threadIdx.x, ty = threadIdx.y;   // (32, 8)
#pragma unroll
    for (int i = 0; i < 4; i++)
        t[ty + i * 8][tx] = src[(long long)(rb + ty + i * 8) * C + cb + tx];
    __syncthreads();
#pragma unroll
    for (int i = 0; i < 4; i++)
        dst[(long long)(cb + ty + i * 8) * R + rb + tx] = __float2half(t[tx][ty + i * 8]);
}

// ---------------- mma / ldmatrix helpers ----------------
__device__ __forceinline__ void ldsm4(unsigned* r, unsigned addr) {
    asm volatile("ldmatrix.sync.aligned.m8n8.x4.shared.b16 {%0,%1,%2,%3}, [%4];"
                 : "=r"(r[0]), "=r"(r[1]), "=r"(r[2]), "=r"(r[3]) : "r"(addr));
}
__device__ __forceinline__ void ldsm4t(unsigned* r, unsigned addr) {
    asm volatile("ldmatrix.sync.aligned.m8n8.x4.trans.shared.b16 {%0,%1,%2,%3}, [%4];"
                 : "=r"(r[0]), "=r"(r[1]), "=r"(r[2]), "=r"(r[3]) : "r"(addr));
}
__device__ __forceinline__ void mma_f16(float* c, const unsigned* a, const unsigned* b) {
    asm volatile(
        "mma.sync.aligned.m16n8k16.row.col.f32.f16.f16.f32 "
        "{%0,%1,%2,%3}, {%4,%5,%6,%7}, {%8,%9}, {%0,%1,%2,%3};"
        : "+f"(c[0]), "+f"(c[1]), "+f"(c[2]), "+f"(c[3])
        : "r"(a[0]), "r"(a[1]), "r"(a[2]), "r"(a[3]), "r"(b[0]), "r"(b[1]));
}
__device__ __forceinline__ void cp16(uint32_t dst, const void* src) {
    asm volatile("cp.async.cg.shared.global [%0], [%1], 16;\n" :: "r"(dst), "l"(src));
}
__device__ __forceinline__ float gelu_f(float x) {
    const float c = 0.7978845608028654f;
    float t = tanhf(c * (x + 0.044715f * x * x * x));
    return 0.5f * x * (1.f + t);
}
__device__ __forceinline__ unsigned pack_h2(float a, float b) {
    __half2 h = __halves2half2(__float2half(a), __float2half(b));
    return *(unsigned*)&h;
}

// ============================================================================
// FP16 tensor-core GEMM (NT): C = alpha*(A @ B^T) [+Cin] [gelu]
// A [M,Kd] fp16 row-major lda, B [N,Kd] fp16 row-major ldb.
// CTA tile 128 x 128, K-tile 32, 256 threads, 2x4 warps (warp 64x32),
// 3-stage cp.async pipeline, ONE __syncthreads per K-tile.
// Stage reuse hazard: stage s is overwritten at iter kt (load kt+2) only after
// this iter's syncthreads, which follows all warps' compute of iter kt-1 that
// last read stage s. Safe.
// ============================================================================
__global__ void __launch_bounds__(256) h_gemm(
    const __half* __restrict__ A, const __half* __restrict__ B,
    const float* __restrict__ Cin, void* __restrict__ CoutV,
    int Kd, int lda, int ldb, int ldc,
    float alpha, int addC, int doGelu, int outHalf)
{
    constexpr int PB2 = 40;                // smem pitch in halves (80 B)
    constexpr int ASZ = 128 * PB2;         // halves per A stage
    constexpr int BSZ = 128 * PB2;         // halves per B stage
    constexpr int STG = ASZ + BSZ;

    extern __shared__ __half dsm[];
    unsigned sb = (unsigned)__cvta_generic_to_shared(dsm);

    const float* CinP = Cin;
    float*  CF = (float*)CoutV;
    __half* CH = (__half*)CoutV;

    int bm = blockIdx.y * 128;
    int bn = blockIdx.x * 128;

    int tid = threadIdx.x;
    int lane = tid & 31;
    int warp = tid >> 5;
    int warpM = (warp >> 2) * 64;
    int warpN = (warp & 3) * 32;

    // ldsm per-lane offsets (stage-relative bytes)
    unsigned aOff[4];
#pragma unroll
    for (int mt = 0; mt < 4; mt++)
        aOff[mt] = (unsigned)(((warpM + mt * 16 + (lane & 15)) * PB2 + (lane >> 4) * 8) * 2);
    unsigned bOff[2];
#pragma unroll
    for (int np = 0; np < 2; np++)
        bOff[np] = (unsigned)(ASZ * 2 +
                   ((warpN + np * 16 + (lane & 7) + ((lane >> 4) & 1) * 8) * PB2
                    + ((lane >> 3) & 1) * 8) * 2);

    float acc[4][4][4];
#pragma unroll
    for (int i = 0; i < 4; i++)
#pragma unroll
        for (int j = 0; j < 4; j++)
#pragma unroll
            for (int q = 0; q < 4; q++) acc[i][j][q] = 0.f;

    int srow = tid >> 1;          // 0..127
    int scp  = (tid & 1) * 2;     // chunk base (2 chunks of 16B per matrix)

    auto load_tile = [&](int kt, int st) {
        int k0 = kt * 32;
        unsigned ab = sb + (unsigned)(st * STG * 2);
        unsigned bb2 = ab + (unsigned)(ASZ * 2);
#pragma unroll
        for (int c = 0; c < 2; c++)
            cp16(ab + (unsigned)((srow * PB2 + (scp + c) * 8) * 2),
                 A + (long long)(bm + srow) * lda + k0 + (scp + c) * 8);
#pragma unroll
        for (int c = 0; c < 2; c++)
            cp16(bb2 + (unsigned)((srow * PB2 + (scp + c) * 8) * 2),
                 B + (long long)(bn + srow) * ldb + k0 + (scp + c) * 8);
        asm volatile("cp.async.commit_group;");
    };

    int KT = Kd >> 5;
    load_tile(0, 0);
    if (KT > 1) load_tile(1, 1);

    for (int kt = 0; kt < KT; kt++) {
        if (kt + 1 < KT) asm volatile("cp.async.wait_group 1;");
        else             asm volatile("cp.async.wait_group 0;");
        __syncthreads();
        if (kt + 2 < KT) load_tile(kt + 2, (kt + 2) % 3);

        unsigned base = sb + (unsigned)((kt % 3) * STG * 2);
#pragma unroll
        for (int k16 = 0; k16 < 2; k16++) {
            unsigned aF[4][4];
#pragma unroll
            for (int mt = 0; mt < 4; mt++)
                ldsm4(aF[mt], base + aOff[mt] + k16 * 32);
            unsigned bF[2][4];
#pragma unroll
            for (int np = 0; np < 2; np++)
                ldsm4(bF[np], base + bOff[np] + k16 * 32);
#pragma unroll
            for (int mt = 0; mt < 4; mt++)
#pragma unroll
                for (int np = 0; np < 2; np++) {
                    mma_f16(acc[mt][np * 2 + 0], aF[mt], &bF[np][0]);
                    mma_f16(acc[mt][np * 2 + 1], aF[mt], &bF[np][2]);
                }
        }
    }

    int grp = lane >> 2, c2 = (lane & 3) * 2;
#pragma unroll
    for (int mt = 0; mt < 4; mt++) {
#pragma unroll
        for (int j = 0; j < 4; j++) {
            int col = bn + warpN + (j >> 1) * 16 + (j & 1) * 8 + c2;
            long long r0 = (long long)(bm + warpM + mt * 16 + grp) * ldc + col;
            long long r1 = r0 + 8LL * ldc;
            float v00 = acc[mt][j][0] * alpha, v01 = acc[mt][j][1] * alpha;
            float v10 = acc[mt][j][2] * alpha, v11 = acc[mt][j][3] * alpha;
            if (doGelu) {
                v00 = gelu_f(v00); v01 = gelu_f(v01);
                v10 = gelu_f(v10); v11 = gelu_f(v11);
            }
            if (addC) {
                float2 ci0 = *(const float2*)(CinP + r0);
                float2 ci1 = *(const float2*)(CinP + r1);
                v00 += ci0.x; v01 += ci0.y;
                v10 += ci1.x; v11 += ci1.y;
            }
            if (outHalf) {
                *(__half2*)(CH + r0) = __halves2half2(__float2half(v00), __float2half(v01));
                *(__half2*)(CH + r1) = __halves2half2(__float2half(v10), __float2half(v11));
            } else {
                *(float2*)(CF + r0) = make_float2(v00, v01);
                *(float2*)(CF + r1) = make_float2(v10, v11);
            }
        }
    }
}

// ============================================================================
// Fused FlashAttention-2 over the active token set (unchanged from R12).
// ============================================================================
#define FPITCH 72   // smem pitch in halves

__global__ void __launch_bounds__(256) flash_kernel(
    const __half* __restrict__ qkv, __half* __restrict__ yout)
{
    extern __shared__ __half fsm[];
    __half* Qs = fsm;
    __half* Ks0 = fsm + 128 * FPITCH;
    __half* Ks1 = fsm + 2 * 128 * FPITCH;
    __half* Vs0 = fsm + 3 * 128 * FPITCH;
    __half* Vs1 = fsm + 4 * 128 * FPITCH;

    int bh = blockIdx.y;
    int b = bh / HH, h = bh % HH;
    const __half* Qg = qkv + (size_t)b * KC * 3 * DD + h * DHH;
    const __half* Kg = Qg + DD;
    const __half* Vg = Qg + 2 * DD;
    int q0 = blockIdx.x * 128;

    int tid = threadIdx.x;
    int lane = tid & 31, warp = tid >> 5;
    int wq = warp * 16;

    unsigned qB = (unsigned)__cvta_generic_to_shared(Qs);
    unsigned kB0 = (unsigned)__cvta_generic_to_shared(Ks0);
    unsigned kB1 = (unsigned)__cvta_generic_to_shared(Ks1);
    unsigned vB0 = (unsigned)__cvta_generic_to_shared(Vs0);
    unsigned vB1 = (unsigned)__cvta_generic_to_shared(Vs1);

    int sr = tid >> 2;           // row 0..63 (+64 second pass)
    int sq = tid & 3;            // chunk-pair index

    auto load_q = [&]() {
#pragma unroll
        for (int p = 0; p < 2; p++)
#pragma unroll
            for (int c = 0; c < 2; c++)
                cp16(qB + (unsigned)(((sr + p * 64) * FPITCH + (sq * 2 + c) * 8) * 2),
                     Qg + (long long)(q0 + sr + p * 64) * (3 * DD) + (sq * 2 + c) * 8);
    };
    auto load_kv = [&](int it, unsigned kb, unsigned vb) {
#pragma unroll
        for (int p = 0; p < 2; p++) {
            int r0 = it * 128 + sr + p * 64;
#pragma unroll
            for (int c = 0; c < 2; c++)
                cp16(kb + (unsigned)(((sr + p * 64) * FPITCH + (sq * 2 + c) * 8) * 2),
                     Kg + (long long)r0 * (3 * DD) + (sq * 2 + c) * 8);
#pragma unroll
            for (int c = 0; c < 2; c++)
                cp16(vb + (unsigned)(((sr + p * 64) * FPITCH + (sq * 2 + c) * 8) * 2),
                     Vg + (long long)r0 * (3 * DD) + (sq * 2 + c) * 8);
        }
    };

    unsigned qAddr = qB + (unsigned)(((wq + (lane & 15)) * FPITCH + (lane >> 4) * 8) * 2);
    unsigned kLane = (unsigned)((((lane & 7) + ((lane >> 4) & 1) * 8) * FPITCH
                                 + ((lane >> 3) & 1) * 8) * 2);
    unsigned vLane = (unsigned)((((lane & 7) + ((lane >> 3) & 1) * 8) * FPITCH
                                 + (lane >> 4) * 8) * 2);

    float m0 = -1e30f, m1 = -1e30f, l0 = 0.f, l1 = 0.f;
    float O[8][4];
#pragma unroll
    for (int i = 0; i < 8; i++)
#pragma unroll
        for (int j = 0; j < 4; j++) O[i][j] = 0.f;

    const float LOG2E = 1.4426950408889634f;

    load_q();
    load_kv(0, kB0, vB0);
    asm volatile("cp.async.commit_group;");

    const int NIT = KC / 128;
    for (int it = 0; it < NIT; it++) {
        asm volatile("cp.async.wait_group 0;");
        __syncthreads();
        unsigned kb = (it & 1) ? kB1 : kB0;
        unsigned vb = (it & 1) ? vB1 : vB0;
        if (it + 1 < NIT) {
            load_kv(it + 1, (it & 1) ? kB0 : kB1, (it & 1) ? vB0 : vB1);
            asm volatile("cp.async.commit_group;");
        }

        float S[16][4];
#pragma unroll
        for (int i = 0; i < 16; i++)
#pragma unroll
            for (int j = 0; j < 4; j++) S[i][j] = 0.f;

#pragma unroll
        for (int dhc = 0; dhc < 4; dhc++) {
            unsigned qa[4];
            ldsm4(qa, qAddr + dhc * 32);
#pragma unroll
            for (int nt = 0; nt < 8; nt++) {
                unsigned kf[4];
                ldsm4(kf, kb + kLane + (unsigned)(nt * 16 * FPITCH * 2 + dhc * 32));
                mma_f16(S[2 * nt], qa, &kf[0]);
                mma_f16(S[2 * nt + 1], qa, &kf[2]);
            }
        }

        float mx0 = -1e30f, mx1 = -1e30f;
#pragma unroll
        for (int i = 0; i < 16; i++) {
#pragma unroll
            for (int j = 0; j < 4; j++) S[i][j] *= 0.125f;
            mx0 = fmaxf(mx0, fmaxf(S[i][0], S[i][1]));
            mx1 = fmaxf(mx1, fmaxf(S[i][2], S[i][3]));
        }
        mx0 = fmaxf(mx0, __shfl_xor_sync(0xffffffffu, mx0, 1));
        mx0 = fmaxf(mx0, __shfl_xor_sync(0xffffffffu, mx0, 2));
        mx1 = fmaxf(mx1, __shfl_xor_sync(0xffffffffu, mx1, 1));
        mx1 = fmaxf(mx1, __shfl_xor_sync(0xffffffffu, mx1, 2));
        float mn0 = fmaxf(m0, mx0), mn1 = fmaxf(m1, mx1);
        float sc0 = exp2f((m0 - mn0) * LOG2E);
        float sc1 = exp2f((m1 - mn1) * LOG2E);
        float sum0 = 0.f, sum1 = 0.f;
#pragma unroll
        for (int i = 0; i < 16; i++) {
            S[i][0] = exp2f((S[i][0] - mn0) * LOG2E);
            S[i][1] = exp2f((S[i][1] - mn0) * LOG2E);
            S[i][2] = exp2f((S[i][2] - mn1) * LOG2E);
            S[i][3] = exp2f((S[i][3] - mn1) * LOG2E);
            sum0 += S[i][0] + S[i][1];
            sum1 += S[i][2] + S[i][3];
        }
        sum0 += __shfl_xor_sync(0xffffffffu, sum0, 1);
        sum0 += __shfl_xor_sync(0xffffffffu, sum0, 2);
        sum1 += __shfl_xor_sync(0xffffffffu, sum1, 1);
        sum1 += __shfl_xor_sync(0xffffffffu, sum1, 2);
        l0 = l0 * sc0 + sum0;
        l1 = l1 * sc1 + sum1;
        m0 = mn0; m1 = mn1;
#pragma unroll
        for (int dn = 0; dn < 8; dn++) {
            O[dn][0] *= sc0; O[dn][1] *= sc0;
            O[dn][2] *= sc1; O[dn][3] *= sc1;
        }

#pragma unroll
        for (int kc = 0; kc < 8; kc++) {
            unsigned pa[4];
            pa[0] = pack_h2(S[2 * kc][0], S[2 * kc][1]);
            pa[1] = pack_h2(S[2 * kc][2], S[2 * kc][3]);
            pa[2] = pack_h2(S[2 * kc + 1][0], S[2 * kc + 1][1]);
            pa[3] = pack_h2(S[2 * kc + 1][2], S[2 * kc + 1][3]);
#pragma unroll
            for (int dn = 0; dn < 4; dn++) {
                unsigned vf[4];
                ldsm4t(vf, vb + vLane + (unsigned)(kc * 16 * FPITCH * 2 + dn * 32));
                mma_f16(O[2 * dn], pa, &vf[0]);
                mma_f16(O[2 * dn + 1], pa, &vf[2]);
            }
        }
        __syncthreads();
    }

    float inv0 = 1.f / l0, inv1 = 1.f / l1;
    int row0 = b * KC + q0 + wq + (lane >> 2);
    int row1 = row0 + 8;
    int colb = h * DHH + (lane & 3) * 2;
#pragma unroll
    for (int dn = 0; dn < 8; dn++) {
        int col = colb + dn * 8;
        *(__half2*)(yout + (size_t)row0 * DD + col) =
            __halves2half2(__float2half(O[dn][0] * inv0), __float2half(O[dn][1] * inv0));
        *(__half2*)(yout + (size_t)row1 * DD + col) =
            __halves2half2(__float2half(O[dn][2] * inv1), __float2half(O[dn][3] * inv1));
    }
}

// ---------------- gated scatter-add ----------------
__global__ void scatter_kernel(float* __restrict__ out) {
    int row = blockIdx.x;
    int b = row / KC;
    int idx = g_sel[row];
    float g = g_gate[row];
    float4* dst = (float4*)(out + ((size_t)b * TT + idx) * DD);
    const float4* src = (const float4*)(g_h + (size_t)row * DD);
    for (int i = threadIdx.x; i < DD / 4; i += blockDim.x) {
        float4 d = dst[i], s = src[i];
        d.x += g * s.x; d.y += g * s.y; d.z += g * s.z; d.w += g * s.w;
        dst[i] = d;
    }
}

// ---------------- host launcher ----------------
extern "C" void kernel_launch(void* const* d_in, const int* in_sizes, int n_in,
                              void* d_out, int out_size) {
    const float* x        = (const float*)d_in[0];
    const float* router_w = (const float*)d_in[1];
    const float* router_b = (const float*)d_in[2];
    const float* ln1_w    = (const float*)d_in[3];
    const float* ln1_b    = (const float*)d_in[4];
    const float* wqkv     = (const float*)d_in[5];
    const float* wo       = (const float*)d_in[6];
    const float* ln2_w    = (const float*)d_in[7];
    const float* ln2_b    = (const float*)d_in[8];
    const float* w1       = (const float*)d_in[9];
    const float* w2       = (const float*)d_in[10];
    float* out = (float*)d_out;

    float *p_h;
    __half *p_y, *p_qkv, *p_ff;
    __half *p_wqkvt, *p_w1t, *p_w2t, *p_wot;
    cudaGetSymbolAddress((void**)&p_h, g_h);
    cudaGetSymbolAddress((void**)&p_y, g_y);
    cudaGetSymbolAddress((void**)&p_qkv, g_qkv);
    cudaGetSymbolAddress((void**)&p_ff, g_ff);
    cudaGetSymbolAddress((void**)&p_wqkvt, g_wqkvt);
    cudaGetSymbolAddress((void**)&p_w1t, g_w1t);
    cudaGetSymbolAddress((void**)&p_w2t, g_w2t);
    cudaGetSymbolAddress((void**)&p_wot, g_wot);

    const int FSMEM = 5 * 128 * FPITCH * 2;            // 92160 B
    const int GSMEM = 3 * (128 + 128) * 40 * 2;        // 61440 B
    cudaFuncSetAttribute(flash_kernel, cudaFuncAttributeMaxDynamicSharedMemorySize, FSMEM);
    cudaFuncSetAttribute(h_gemm, cudaFuncAttributeMaxDynamicSharedMemorySize, GSMEM);

    router_kernel<<<BB * TT, 256>>>(x, router_w, router_b);
    topk_kernel<<<BB, 1024>>>();
    gather_kernel<<<MR, 256>>>(x);

    // pre-transpose + fp16-convert weights: W[K,N] -> Wt[N,K]
    dim3 tb(32, 8);
    transpose_w<<<dim3(3 * DD / 32, DD / 32, LL), tb>>>(
        wqkv, p_wqkvt, DD, 3 * DD, (long long)DD * 3 * DD, (long long)3 * DD * DD);
    transpose_w<<<dim3(FF / 32, DD / 32, LL), tb>>>(
        w1, p_w1t, DD, FF, (long long)DD * FF, (long long)FF * DD);
    transpose_w<<<dim3(DD / 32, FF / 32, LL), tb>>>(
        w2, p_w2t, FF, DD, (long long)FF * DD, (long long)DD * FF);
    transpose_w<<<dim3(DD / 32, DD / 32, LL), tb>>>(
        wo, p_wot, DD, DD, (long long)DD * DD, (long long)DD * DD);

    for (int l = 0; l < LL; l++) {
        // --- attention sub-block ---
        ln_kernel<<<MR, 256>>>(p_h, ln1_w + l * DD, ln1_b + l * DD, p_y);

        // qkv = y @ Wqkv^T  (fp16 out)
        h_gemm<<<dim3(3 * DD / 128, MR / 128, 1), 256, GSMEM>>>(
            p_y, p_wqkvt + (size_t)l * 3 * DD * DD, p_h, p_qkv,
            DD, DD, DD, 3 * DD, 1.f, 0, 0, 1);

        // fused attention -> y (fp16)
        flash_kernel<<<dim3(KC / 128, BB * HH), 256, FSMEM>>>(p_qkv, p_y);

        // h += O @ Wo^T (fp32 out + residual)
        h_gemm<<<dim3(DD / 128, MR / 128, 1), 256, GSMEM>>>(
            p_y, p_wot + (size_t)l * DD * DD, p_h, p_h,
            DD, DD, DD, DD, 1.f, 1, 0, 0);

        // --- MLP sub-block ---
        ln_kernel<<<MR, 256>>>(p_h, ln2_w + l * DD, ln2_b + l * DD, p_y);

        // ff = gelu(y @ W1^T)  (fp16 out, gelu fused)
        h_gemm<<<dim3(FF / 128, MR / 128, 1), 256, GSMEM>>>(
            p_y, p_w1t + (size_t)l * FF * DD, p_h, p_ff,
            DD, DD, DD, FF, 1.f, 0, 1, 1);

        // h += ff @ W2^T (fp32 out + residual)
        h_gemm<<<dim3(DD / 128, MR / 128, 1), 256, GSMEM>>>(
            p_ff, p_w2t + (size_t)l * DD * FF, p_h, p_h,
            FF, FF, FF, DD, 1.f, 1, 0, 0);
    }

    cudaMemcpyAsync(out, x, (size_t)BB * TT * DD * sizeof(float),
                    cudaMemcpyDeviceToDevice, 0);
    scatter_kernel<<<MR, 256>>>(out);
}